// round 13
// baseline (speedup 1.0000x reference)
#include <cuda_runtime.h>
#include <cuda_bf16.h>
#include <math.h>
#include <stdint.h>

// Problem constants
#define BSZ 4
#define TLEN 2048
#define DM 1024
#define DI 2048
#define DS 16
#define DC 4
#define MROWS (BSZ * TLEN)        // 8192
#define NC 64                      // scan chunks
#define CL 32                      // chunk length

// -------- scratch (device globals) --------
__device__ float g_xz[(size_t)MROWS * 2 * DI];
__device__ float g_xconv[(size_t)MROWS * DI];
__device__ float g_alpha[MROWS];
__device__ float g_S[(size_t)BSZ * NC * DI];
__device__ float g_H0[(size_t)BSZ * NC * DI];
__device__ __nv_bfloat16 g_xh[(size_t)MROWS * DM],  g_xl[(size_t)MROWS * DM];
__device__ __nv_bfloat16 g_wih[(size_t)2 * DI * DM], g_wil[(size_t)2 * DI * DM];
__device__ __nv_bfloat16 g_yh[(size_t)MROWS * DI],  g_yl[(size_t)MROWS * DI];
__device__ __nv_bfloat16 g_woh[(size_t)DM * DI],    g_wol[(size_t)DM * DI];
__device__ __nv_bfloat16 g_xch[(size_t)MROWS * DI];
__device__ __nv_bfloat16 g_xpwh[(size_t)DS * DI];
__device__ __nv_bfloat16 g_dtwh[(size_t)DI * DS];

// ============================ helpers =======================================
__device__ __forceinline__ uint32_t smem_u32(const void* p) {
    uint32_t a;
    asm("{ .reg .u64 t; cvta.to.shared.u64 t, %1; cvt.u32.u64 %0, t; }"
        : "=r"(a) : "l"(p));
    return a;
}
__device__ __forceinline__ void ldx4(uint32_t* r, uint32_t addr) {
    asm volatile("ldmatrix.sync.aligned.m8n8.x4.shared.b16 {%0,%1,%2,%3}, [%4];"
        : "=r"(r[0]), "=r"(r[1]), "=r"(r[2]), "=r"(r[3]) : "r"(addr));
}
__device__ __forceinline__ void mma16816(float* c, const uint32_t* a,
                                         uint32_t b0, uint32_t b1) {
    asm volatile(
        "mma.sync.aligned.m16n8k16.row.col.f32.bf16.bf16.f32 "
        "{%0,%1,%2,%3}, {%4,%5,%6,%7}, {%8,%9}, {%0,%1,%2,%3};"
        : "+f"(c[0]), "+f"(c[1]), "+f"(c[2]), "+f"(c[3])
        : "r"(a[0]), "r"(a[1]), "r"(a[2]), "r"(a[3]), "r"(b0), "r"(b1));
}
__device__ __forceinline__ void cp16(uint32_t s, const void* g) {
    asm volatile("cp.async.cg.shared.global [%0], [%1], 16;"
        :: "r"(s), "l"(g) : "memory");
}
__device__ __forceinline__ float sigmoidf_(float v) { return 1.f / (1.f + __expf(-v)); }
__device__ __forceinline__ float siluf_(float v)    { return v * sigmoidf_(v); }
__device__ __forceinline__ float softplusf_(float v) {
    return (v > 20.f) ? v : __logf(1.f + __expf(v));
}
__device__ __forceinline__ uint32_t packbf2(float a, float b) {
    __nv_bfloat162 t = __floats2bfloat162_rn(a, b);
    return *(uint32_t*)&t;
}
__device__ __forceinline__ uint32_t swz64(uint32_t o) {
    return o ^ ((o >> 3) & 0x30);
}

// ---------------------------------------------------------------------------
// Merged operand conversion: x/win/wout split hi+lo; xpw/dtw hi only.
// ---------------------------------------------------------------------------
#define CV_N0 (MROWS * DM / 4)
#define CV_N1 (CV_N0 + 2 * DI * DM / 4)
#define CV_N2 (CV_N1 + DM * DI / 4)
#define CV_N3 (CV_N2 + DS * DI / 4)
#define CV_N4 (CV_N3 + DI * DS / 4)

__global__ __launch_bounds__(256) void cvt_all_kernel(
    const float* __restrict__ x, const float* __restrict__ win,
    const float* __restrict__ wout, const float* __restrict__ xpw,
    const float* __restrict__ dtw)
{
    int i = blockIdx.x * 256 + threadIdx.x;
    if (i >= CV_N4) return;
    const float* src; __nv_bfloat16 *hi, *lo; int j; bool split = true;
    if (i < CV_N0)      { j = i;         src = x;    hi = g_xh;  lo = g_xl;  }
    else if (i < CV_N1) { j = i - CV_N0; src = win;  hi = g_wih; lo = g_wil; }
    else if (i < CV_N2) { j = i - CV_N1; src = wout; hi = g_woh; lo = g_wol; }
    else if (i < CV_N3) { j = i - CV_N2; src = xpw;  hi = g_xpwh; lo = 0; split = false; }
    else                { j = i - CV_N3; src = dtw;  hi = g_dtwh; lo = 0; split = false; }
    float4 v = ((const float4*)src)[j];
    float vv[4] = {v.x, v.y, v.z, v.w};
    __nv_bfloat16 h[4], l[4];
#pragma unroll
    for (int k = 0; k < 4; k++) {
        h[k] = __float2bfloat16_rn(vv[k]);
        l[k] = __float2bfloat16_rn(vv[k] - __bfloat162float(h[k]));
    }
    ((uint2*)hi)[j] = *(uint2*)h;
    if (split) ((uint2*)lo)[j] = *(uint2*)l;
}

// ---------------------------------------------------------------------------
// Split-bf16 NT GEMM via mma.sync. CTA tile 256x128, 256 threads, 8 warps
// (4x2), warp tile 64x64: halves SMEM bytes/output vs 128x128 configs.
// 3-stage cp.async (144KB), swizzled SMEM, one barrier/chunk, term-major.
// ---------------------------------------------------------------------------
#define KC      32
#define A_TILEB (256 * 64)            // 16384
#define B_TILEB (128 * 64)            // 8192
#define STGB    (2 * A_TILEB + 2 * B_TILEB)   // 49152
#define NSTG    3
#define GSMEM   (NSTG * STGB)         // 147456

__global__ void __launch_bounds__(256, 1) gemm3_bf(
    const __nv_bfloat16* __restrict__ Ah_, const __nv_bfloat16* __restrict__ Al_,
    const __nv_bfloat16* __restrict__ Bh_, const __nv_bfloat16* __restrict__ Bl_,
    float* __restrict__ C, int N, int K)
{
    extern __shared__ char smem[];
    const uint32_t sb = smem_u32(smem);
    const int tid = threadIdx.x, lane = tid & 31, wid = tid >> 5;
    const int bm = blockIdx.y, bn = blockIdx.x;
    const int warp_m = wid >> 1, warp_n = wid & 1;   // 4 x 2 warps, 64x64 tiles

    // cp.async source/dest mapping:
    //  A: one 256-elem... each thread owns row tid (4 x 16B units per tile)
    //  B: each thread owns 2 units (512 units per tile / 256 threads)
    const size_t a_src = (size_t)(bm * 256 + tid) * K;
    const int bu = tid * 2;
    const size_t b_src0 = (size_t)(bn * 128 + (bu >> 2)) * K + (bu & 3) * 8;
    const size_t b_src1 = (size_t)(bn * 128 + ((bu + 1) >> 2)) * K + ((bu + 1) & 3) * 8;
    const uint32_t b_dst0 = swz64((uint32_t)((bu >> 2) * 64 + (bu & 3) * 16));
    const uint32_t b_dst1 = swz64((uint32_t)(((bu + 1) >> 2) * 64 + ((bu + 1) & 3) * 16));

    float acc[4][8][4];
#pragma unroll
    for (int i = 0; i < 4; i++)
#pragma unroll
        for (int j = 0; j < 8; j++)
#pragma unroll
            for (int q = 0; q < 4; q++) acc[i][j][q] = 0.f;

    const int nch = K / KC;

#define ISSUE(ch, stg) do { \
        uint32_t dst = sb + (uint32_t)(stg) * STGB; \
        size_t koff = (size_t)(ch) * KC; \
        _Pragma("unroll") \
        for (int j = 0; j < 4; j++) { \
            uint32_t ad = dst + swz64((uint32_t)(tid * 64 + j * 16)); \
            cp16(ad,            Ah_ + a_src + koff + j * 8); \
            cp16(ad + A_TILEB,  Al_ + a_src + koff + j * 8); \
        } \
        cp16(dst + 2 * A_TILEB + b_dst0,           Bh_ + b_src0 + koff); \
        cp16(dst + 2 * A_TILEB + b_dst1,           Bh_ + b_src1 + koff); \
        cp16(dst + 2 * A_TILEB + B_TILEB + b_dst0, Bl_ + b_src0 + koff); \
        cp16(dst + 2 * A_TILEB + B_TILEB + b_dst1, Bl_ + b_src1 + koff); \
        asm volatile("cp.async.commit_group;" ::: "memory"); \
    } while (0)

    ISSUE(0, 0);
    ISSUE(1, 1);

    const uint32_t lrow = lane & 15, lcolb = (lane >> 4) * 16;

    int cs = 0, is = 2;
    for (int ch = 0; ch < nch; ch++) {
        if (ch + 1 < nch)
            asm volatile("cp.async.wait_group 1;" ::: "memory");
        else
            asm volatile("cp.async.wait_group 0;" ::: "memory");
        __syncthreads();
        if (ch + 2 < nch) {
            ISSUE(ch + 2, is);
            is = (is == 2) ? 0 : is + 1;
        }

        const uint32_t st = sb + (uint32_t)cs * STGB;
        cs = (cs == 2) ? 0 : cs + 1;
#pragma unroll
        for (int ks = 0; ks < 2; ks++) {
            uint32_t Ahf[4][4], Alf[4][4], Bhf[8][2], Blf[8][2];
#pragma unroll
            for (int ma = 0; ma < 4; ma++) {
                uint32_t alog = (uint32_t)((warp_m * 64 + ma * 16 + lrow) * 64
                                           + ks * 32) + lcolb;
                uint32_t ad = st + swz64(alog);
                ldx4(Ahf[ma], ad);
                ldx4(Alf[ma], ad + A_TILEB);
            }
#pragma unroll
            for (int p = 0; p < 4; p++) {
                uint32_t blog = (uint32_t)((warp_n * 64 + p * 16 + lrow) * 64
                                           + ks * 32) + lcolb;
                uint32_t bd = st + 2 * A_TILEB + swz64(blog);
                uint32_t q[4];
                ldx4(q, bd);
                Bhf[2 * p][0] = q[0]; Bhf[2 * p][1] = q[2];
                Bhf[2 * p + 1][0] = q[1]; Bhf[2 * p + 1][1] = q[3];
                ldx4(q, bd + B_TILEB);
                Blf[2 * p][0] = q[0]; Blf[2 * p][1] = q[2];
                Blf[2 * p + 1][0] = q[1]; Blf[2 * p + 1][1] = q[3];
            }
            // term-major MMA bursts (96 MMAs per ks)
#pragma unroll
            for (int ma = 0; ma < 4; ma++)
#pragma unroll
                for (int na = 0; na < 8; na++)
                    mma16816(acc[ma][na], Ahf[ma], Bhf[na][0], Bhf[na][1]);
#pragma unroll
            for (int ma = 0; ma < 4; ma++)
#pragma unroll
                for (int na = 0; na < 8; na++)
                    mma16816(acc[ma][na], Alf[ma], Bhf[na][0], Bhf[na][1]);
#pragma unroll
            for (int ma = 0; ma < 4; ma++)
#pragma unroll
                for (int na = 0; na < 8; na++)
                    mma16816(acc[ma][na], Ahf[ma], Blf[na][0], Blf[na][1]);
        }
    }
#undef ISSUE

    const int row_b = bm * 256 + warp_m * 64 + (lane >> 2);
    const int col_b = bn * 128 + warp_n * 64 + ((lane & 3) << 1);
#pragma unroll
    for (int ma = 0; ma < 4; ma++) {
#pragma unroll
        for (int na = 0; na < 8; na++) {
            float* c0 = C + (size_t)(row_b + ma * 16) * N + col_b + na * 8;
            float* c1 = c0 + (size_t)8 * N;
            *(float2*)c0 = make_float2(acc[ma][na][0], acc[ma][na][1]);
            *(float2*)c1 = make_float2(acc[ma][na][2], acc[ma][na][3]);
        }
    }
}

// ============================ elementwise / scan =============================
__global__ __launch_bounds__(256) void conv_silu_kernel(
    const float* __restrict__ cw, const float* __restrict__ cb)
{
    const int d  = blockIdx.x * 256 + threadIdx.x;
    const int b  = blockIdx.z;
    const int t0 = blockIdx.y * 32;
    const float* xin = g_xz + (size_t)b * TLEN * (2 * DI) + d;
    float* xco = g_xconv + ((size_t)b * TLEN + t0) * DI + d;
    __nv_bfloat16* xch = g_xch + ((size_t)b * TLEN + t0) * DI + d;

    const float w0 = cw[d * 4 + 0], w1 = cw[d * 4 + 1];
    const float w2 = cw[d * 4 + 2], w3 = cw[d * 4 + 3];
    const float bias = cb[d];

    float xm3 = (t0 - 3 >= 0) ? xin[(size_t)(t0 - 3) * (2 * DI)] : 0.f;
    float xm2 = (t0 - 2 >= 0) ? xin[(size_t)(t0 - 2) * (2 * DI)] : 0.f;
    float xm1 = (t0 - 1 >= 0) ? xin[(size_t)(t0 - 1) * (2 * DI)] : 0.f;
#pragma unroll 4
    for (int tt = 0; tt < 32; tt++) {
        float xc = xin[(size_t)(t0 + tt) * (2 * DI)];
        float v = w0 * xm3 + w1 * xm2 + w2 * xm1 + w3 * xc + bias;
        float s = siluf_(v);
        xco[(size_t)tt * DI] = s;
        xch[(size_t)tt * DI] = __float2bfloat16_rn(s);
        xm3 = xm2; xm2 = xm1; xm1 = xc;
    }
}

// ---------------------------------------------------------------------------
// Fused B_ssm + dt + alpha. 512 blocks x 16 rows; warps split K 8-ways for
// the B_ssm MMA (SMEM-reduced) then split the dt loop 8-ways.
// ---------------------------------------------------------------------------
__global__ __launch_bounds__(256) void proj_alpha_kernel(const float* __restrict__ dtb)
{
    __shared__ float red[8][32][9];
    __shared__ float rsum[16];
    const int lane = threadIdx.x & 31, wid = threadIdx.x >> 5;
    const int rowbase = blockIdx.x * 16;
    const int r0 = rowbase + (lane >> 2);
    const int k0l = (lane & 3) * 2;
    const int nfr = (lane >> 2);
    const __nv_bfloat16* xr0 = g_xch + (size_t)r0 * DI;
    const __nv_bfloat16* xr8 = xr0 + (size_t)8 * DI;

    float c[2][4];
#pragma unroll
    for (int nt = 0; nt < 2; nt++)
#pragma unroll
        for (int q = 0; q < 4; q++) c[nt][q] = 0.f;

    const int ksbase = wid * 16;
#pragma unroll 4
    for (int ks = 0; ks < 16; ks++) {
        const int k0 = (ksbase + ks) * 16 + k0l;
        uint32_t a[4];
        a[0] = *(const uint32_t*)(xr0 + k0);
        a[1] = *(const uint32_t*)(xr8 + k0);
        a[2] = *(const uint32_t*)(xr0 + k0 + 8);
        a[3] = *(const uint32_t*)(xr8 + k0 + 8);
#pragma unroll
        for (int nt = 0; nt < 2; nt++) {
            const __nv_bfloat16* wn = g_xpwh + (size_t)(nt * 8 + nfr) * DI + k0;
            uint32_t b0 = *(const uint32_t*)(wn);
            uint32_t b1 = *(const uint32_t*)(wn + 8);
            mma16816(c[nt], a, b0, b1);
        }
    }
#pragma unroll
    for (int j = 0; j < 4; j++) {
        red[wid][lane][j]     = c[0][j];
        red[wid][lane][4 + j] = c[1][j];
    }
    if (threadIdx.x < 16) rsum[threadIdx.x] = 0.f;
    __syncthreads();

    float cf[8];
#pragma unroll
    for (int j = 0; j < 8; j++) {
        float s = 0.f;
#pragma unroll
        for (int w = 0; w < 8; w++) s += red[w][lane][j];
        cf[j] = s;
    }
    uint32_t a2[4];
    a2[0] = packbf2(cf[0], cf[1]);
    a2[1] = packbf2(cf[2], cf[3]);
    a2[2] = packbf2(cf[4], cf[5]);
    a2[3] = packbf2(cf[6], cf[7]);

    float sumA = 0.f, sumB = 0.f;
    const int ndbase = wid * 32;
#pragma unroll 4
    for (int nd = ndbase; nd < ndbase + 32; nd++) {
        const int n = nd * 8 + nfr;
        const __nv_bfloat16* wn = g_dtwh + (size_t)n * DS;
        uint32_t b0 = *(const uint32_t*)(wn + k0l);
        uint32_t b1 = *(const uint32_t*)(wn + k0l + 8);
        float cc[4] = {0.f, 0.f, 0.f, 0.f};
        mma16816(cc, a2, b0, b1);
        const int ncx = nd * 8 + k0l;
        float bb0 = dtb[ncx], bb1 = dtb[ncx + 1];
        sumA += softplusf_(cc[0] + bb0) + softplusf_(cc[1] + bb1);
        sumB += softplusf_(cc[2] + bb0) + softplusf_(cc[3] + bb1);
    }
    sumA += __shfl_xor_sync(0xffffffffu, sumA, 1);
    sumA += __shfl_xor_sync(0xffffffffu, sumA, 2);
    sumB += __shfl_xor_sync(0xffffffffu, sumB, 1);
    sumB += __shfl_xor_sync(0xffffffffu, sumB, 2);
    if ((lane & 3) == 0) {
        atomicAdd(&rsum[lane >> 2], sumA);
        atomicAdd(&rsum[8 + (lane >> 2)], sumB);
    }
    __syncthreads();
    if (threadIdx.x < 16)
        g_alpha[rowbase + threadIdx.x] =
            sigmoidf_(rsum[threadIdx.x] * (1.f / (float)DI));
}

__global__ __launch_bounds__(256) void scan1_kernel()
{
    const int d = blockIdx.x * 256 + threadIdx.x;
    const int c = blockIdx.y, b = blockIdx.z;
    const float* xc = g_xconv + ((size_t)b * TLEN + c * CL) * DI + d;
    const float* al = g_alpha + b * TLEN + c * CL;
    float h = 0.f;
#pragma unroll 8
    for (int tt = 0; tt < CL; tt++) {
        float a = al[tt];
        h = fmaf(a, h, (1.f - a) * xc[(size_t)tt * DI]);
    }
    g_S[((size_t)(b * NC + c)) * DI + d] = h;
}

__global__ __launch_bounds__(256) void scan2_kernel()
{
    const int id = blockIdx.x * 256 + threadIdx.x;
    const int b = id / DI, d = id % DI;
    __shared__ float Ps[NC];
    if (threadIdx.x < NC) {
        const float* al = g_alpha + b * TLEN + threadIdx.x * CL;
        float p = 1.f;
#pragma unroll
        for (int tt = 0; tt < CL; tt++) p *= al[tt];
        Ps[threadIdx.x] = p;
    }
    __syncthreads();
    float h = 0.f;
    g_H0[((size_t)(b * NC + 0)) * DI + d] = 0.f;
#pragma unroll 4
    for (int c = 0; c < NC - 1; c++) {
        h = fmaf(Ps[c], h, g_S[((size_t)(b * NC + c)) * DI + d]);
        g_H0[((size_t)(b * NC + c + 1)) * DI + d] = h;
    }
}

__global__ __launch_bounds__(256) void scan3_kernel(const float* __restrict__ Dp)
{
    const int d = blockIdx.x * 256 + threadIdx.x;
    const int c = blockIdx.y, b = blockIdx.z;
    const size_t rbase = (size_t)b * TLEN + c * CL;
    const float* xc = g_xconv + rbase * DI + d;
    const float* zp = g_xz + rbase * (2 * DI) + DI + d;
    const float* al = g_alpha + b * TLEN + c * CL;
    __nv_bfloat16* yh = g_yh + rbase * DI + d;
    __nv_bfloat16* yl = g_yl + rbase * DI + d;
    const float Dv = Dp[d];
    float h = g_H0[((size_t)(b * NC + c)) * DI + d];
#pragma unroll 4
    for (int tt = 0; tt < CL; tt++) {
        float a = al[tt];
        float x = xc[(size_t)tt * DI];
        h = fmaf(a, h, (1.f - a) * x);
        float y = fmaf(h, Dv, x);
        float z = zp[(size_t)tt * (2 * DI)];
        y = y * siluf_(z);
        __nv_bfloat16 hh = __float2bfloat16_rn(y);
        yh[(size_t)tt * DI] = hh;
        yl[(size_t)tt * DI] = __float2bfloat16_rn(y - __bfloat162float(hh));
    }
}

// ---------------------------------------------------------------------------
extern "C" void kernel_launch(void* const* d_in, const int* in_sizes, int n_in,
                              void* d_out, int out_size)
{
    const float* x    = (const float*)d_in[0];
    const float* win  = (const float*)d_in[1];
    const float* cw   = (const float*)d_in[2];
    const float* cb   = (const float*)d_in[3];
    const float* xpw  = (const float*)d_in[4];
    const float* dtw  = (const float*)d_in[5];
    const float* dtb  = (const float*)d_in[6];
    const float* Dp   = (const float*)d_in[7];
    const float* wout = (const float*)d_in[8];
    float* out = (float*)d_out;

    float* xz; cudaGetSymbolAddress((void**)&xz, g_xz);
    __nv_bfloat16 *xh, *xl, *wih, *wil, *yh, *yl, *woh, *wol;
    cudaGetSymbolAddress((void**)&xh,  g_xh);
    cudaGetSymbolAddress((void**)&xl,  g_xl);
    cudaGetSymbolAddress((void**)&wih, g_wih);
    cudaGetSymbolAddress((void**)&wil, g_wil);
    cudaGetSymbolAddress((void**)&yh,  g_yh);
    cudaGetSymbolAddress((void**)&yl,  g_yl);
    cudaGetSymbolAddress((void**)&woh, g_woh);
    cudaGetSymbolAddress((void**)&wol, g_wol);

    cudaFuncSetAttribute(gemm3_bf, cudaFuncAttributeMaxDynamicSharedMemorySize,
                         GSMEM);

    // 0) all operand conversions in one launch
    cvt_all_kernel<<<(CV_N4 + 255) / 256, 256>>>(x, win, wout, xpw, dtw);
    // 1) in_proj: M tile 256 -> grid 32x32
    gemm3_bf<<<dim3((2 * DI) / 128, MROWS / 256), 256, GSMEM>>>(
        xh, xl, wih, wil, xz, 2 * DI, DM);
    // 2) depthwise causal conv + SiLU
    conv_silu_kernel<<<dim3(DI / 256, TLEN / 32, BSZ), 256>>>(cw, cb);
    // 3) fused B_ssm + dt + alpha
    proj_alpha_kernel<<<MROWS / 16, 256>>>(dtb);
    // 4) chunked scan
    scan1_kernel<<<dim3(DI / 256, NC, BSZ), 256>>>();
    scan2_kernel<<<MROWS / 256, 256>>>();
    scan3_kernel<<<dim3(DI / 256, NC, BSZ), 256>>>(Dp);
    // 5) out_proj: grid 8x32
    gemm3_bf<<<dim3(DM / 128, MROWS / 256), 256, GSMEM>>>(
        yh, yl, woh, wol, out, DM, DI);
}

// round 14
// speedup vs baseline: 1.2495x; 1.2495x over previous
#include <cuda_runtime.h>
#include <cuda_bf16.h>
#include <math.h>
#include <stdint.h>

// Problem constants
#define BSZ 4
#define TLEN 2048
#define DM 1024
#define DI 2048
#define DS 16
#define DC 4
#define MROWS (BSZ * TLEN)        // 8192
#define NC 64                      // scan chunks
#define CL 32                      // chunk length

// -------- scratch (device globals) --------
__device__ float g_xz[(size_t)MROWS * 2 * DI];
__device__ float g_xconv[(size_t)MROWS * DI];
__device__ float g_alpha[MROWS];
__device__ float g_S[(size_t)BSZ * NC * DI];
__device__ float g_H0[(size_t)BSZ * NC * DI];
__device__ __nv_bfloat16 g_xh[(size_t)MROWS * DM],  g_xl[(size_t)MROWS * DM];
__device__ __nv_bfloat16 g_wih[(size_t)2 * DI * DM], g_wil[(size_t)2 * DI * DM];
__device__ __nv_bfloat16 g_yh[(size_t)MROWS * DI],  g_yl[(size_t)MROWS * DI];
__device__ __nv_bfloat16 g_woh[(size_t)DM * DI],    g_wol[(size_t)DM * DI];
__device__ __nv_bfloat16 g_xch[(size_t)MROWS * DI];
__device__ __nv_bfloat16 g_xpwh[(size_t)DS * DI];
__device__ __nv_bfloat16 g_dtwh[(size_t)DI * DS];

// ============================ helpers =======================================
__device__ __forceinline__ uint32_t smem_u32(const void* p) {
    uint32_t a;
    asm("{ .reg .u64 t; cvta.to.shared.u64 t, %1; cvt.u32.u64 %0, t; }"
        : "=r"(a) : "l"(p));
    return a;
}
__device__ __forceinline__ void ldx4(uint32_t* r, uint32_t addr) {
    asm volatile("ldmatrix.sync.aligned.m8n8.x4.shared.b16 {%0,%1,%2,%3}, [%4];"
        : "=r"(r[0]), "=r"(r[1]), "=r"(r[2]), "=r"(r[3]) : "r"(addr));
}
__device__ __forceinline__ void mma16816(float* c, const uint32_t* a,
                                         uint32_t b0, uint32_t b1) {
    asm volatile(
        "mma.sync.aligned.m16n8k16.row.col.f32.bf16.bf16.f32 "
        "{%0,%1,%2,%3}, {%4,%5,%6,%7}, {%8,%9}, {%0,%1,%2,%3};"
        : "+f"(c[0]), "+f"(c[1]), "+f"(c[2]), "+f"(c[3])
        : "r"(a[0]), "r"(a[1]), "r"(a[2]), "r"(a[3]), "r"(b0), "r"(b1));
}
__device__ __forceinline__ void cp16(uint32_t s, const void* g) {
    asm volatile("cp.async.cg.shared.global [%0], [%1], 16;"
        :: "r"(s), "l"(g) : "memory");
}
__device__ __forceinline__ float sigmoidf_(float v) { return 1.f / (1.f + __expf(-v)); }
__device__ __forceinline__ float siluf_(float v)    { return v * sigmoidf_(v); }
__device__ __forceinline__ float softplusf_(float v) {
    return (v > 20.f) ? v : __logf(1.f + __expf(v));
}
__device__ __forceinline__ uint32_t packbf2(float a, float b) {
    __nv_bfloat162 t = __floats2bfloat162_rn(a, b);
    return *(uint32_t*)&t;
}
__device__ __forceinline__ uint32_t swz128(uint32_t o) {
    return o ^ ((o >> 3) & 0x70);
}

// ---------------------------------------------------------------------------
// Merged operand conversion: x/win/wout split hi+lo; xpw/dtw hi only.
// ---------------------------------------------------------------------------
#define CV_N0 (MROWS * DM / 4)
#define CV_N1 (CV_N0 + 2 * DI * DM / 4)
#define CV_N2 (CV_N1 + DM * DI / 4)
#define CV_N3 (CV_N2 + DS * DI / 4)
#define CV_N4 (CV_N3 + DI * DS / 4)

__global__ __launch_bounds__(256) void cvt_all_kernel(
    const float* __restrict__ x, const float* __restrict__ win,
    const float* __restrict__ wout, const float* __restrict__ xpw,
    const float* __restrict__ dtw)
{
    int i = blockIdx.x * 256 + threadIdx.x;
    if (i >= CV_N4) return;
    const float* src; __nv_bfloat16 *hi, *lo; int j; bool split = true;
    if (i < CV_N0)      { j = i;         src = x;    hi = g_xh;  lo = g_xl;  }
    else if (i < CV_N1) { j = i - CV_N0; src = win;  hi = g_wih; lo = g_wil; }
    else if (i < CV_N2) { j = i - CV_N1; src = wout; hi = g_woh; lo = g_wol; }
    else if (i < CV_N3) { j = i - CV_N2; src = xpw;  hi = g_xpwh; lo = 0; split = false; }
    else                { j = i - CV_N3; src = dtw;  hi = g_dtwh; lo = 0; split = false; }
    float4 v = ((const float4*)src)[j];
    float vv[4] = {v.x, v.y, v.z, v.w};
    __nv_bfloat16 h[4], l[4];
#pragma unroll
    for (int k = 0; k < 4; k++) {
        h[k] = __float2bfloat16_rn(vv[k]);
        l[k] = __float2bfloat16_rn(vv[k] - __bfloat162float(h[k]));
    }
    ((uint2*)hi)[j] = *(uint2*)h;
    if (split) ((uint2*)lo)[j] = *(uint2*)l;
}

// ---------------------------------------------------------------------------
// Split-bf16 NT GEMM via mma.sync. CTA 128x128, 512 threads (4x4 warps,
// 32x32 warp tiles). KC=64 (SW128 rows): halves pipeline sync points vs
// KC=32. 3-stage cp.async (192KB), term-major MMA order. Optional fused
// silu for columns >= zcol0 (in_proj z-half).
// ---------------------------------------------------------------------------
#define KC    64
#define TILEB (128 * 128)          // 16384
#define STGB  (4 * TILEB)          // 65536
#define NSTG  3
#define GSMEM (NSTG * STGB)        // 196608

__global__ void __launch_bounds__(512, 1) gemm3_bf(
    const __nv_bfloat16* __restrict__ Ah_, const __nv_bfloat16* __restrict__ Al_,
    const __nv_bfloat16* __restrict__ Bh_, const __nv_bfloat16* __restrict__ Bl_,
    float* __restrict__ C, int N, int K, int zcol0)
{
    extern __shared__ char smem[];
    const uint32_t sb = smem_u32(smem);
    const int tid = threadIdx.x, lane = tid & 31, wid = tid >> 5;
    const int bm = blockIdx.y, bn = blockIdx.x;
    const int warp_m = wid >> 2, warp_n = wid & 3;   // 4 x 4 warps

    // cp.async mapping: 4 threads per 128B row; each owns units (cu, cu+4)
    const int crow = tid >> 2, cu = tid & 3;
    const uint32_t d0 = swz128((uint32_t)(crow * 128 + cu * 16));
    const uint32_t d1 = swz128((uint32_t)(crow * 128 + (cu + 4) * 16));
    const size_t a_src = (size_t)(bm * 128 + crow) * K + cu * 8;
    const size_t b_src = (size_t)(bn * 128 + crow) * K + cu * 8;

    float acc[2][4][4];
#pragma unroll
    for (int i = 0; i < 2; i++)
#pragma unroll
        for (int j = 0; j < 4; j++)
#pragma unroll
            for (int q = 0; q < 4; q++) acc[i][j][q] = 0.f;

    const int nch = K / KC;

#define ISSUE(ch, stg) do { \
        uint32_t dst = sb + (uint32_t)(stg) * STGB; \
        size_t koff = (size_t)(ch) * KC; \
        cp16(dst + 0 * TILEB + d0, Ah_ + a_src + koff); \
        cp16(dst + 0 * TILEB + d1, Ah_ + a_src + koff + 32); \
        cp16(dst + 1 * TILEB + d0, Al_ + a_src + koff); \
        cp16(dst + 1 * TILEB + d1, Al_ + a_src + koff + 32); \
        cp16(dst + 2 * TILEB + d0, Bh_ + b_src + koff); \
        cp16(dst + 2 * TILEB + d1, Bh_ + b_src + koff + 32); \
        cp16(dst + 3 * TILEB + d0, Bl_ + b_src + koff); \
        cp16(dst + 3 * TILEB + d1, Bl_ + b_src + koff + 32); \
        asm volatile("cp.async.commit_group;" ::: "memory"); \
    } while (0)

    ISSUE(0, 0);
    ISSUE(1, 1);

    const uint32_t lrow = lane & 15, lcolb = (lane >> 4) * 16;

    int cs = 0, is = 2;
    for (int ch = 0; ch < nch; ch++) {
        if (ch + 1 < nch)
            asm volatile("cp.async.wait_group 1;" ::: "memory");
        else
            asm volatile("cp.async.wait_group 0;" ::: "memory");
        __syncthreads();
        if (ch + 2 < nch) {
            ISSUE(ch + 2, is);
            is = (is == 2) ? 0 : is + 1;
        }

        const uint32_t st = sb + (uint32_t)cs * STGB;
        cs = (cs == 2) ? 0 : cs + 1;
#pragma unroll
        for (int ks = 0; ks < 4; ks++) {
            uint32_t Ahf[2][4], Alf[2][4], Bhf[4][2], Blf[4][2];
#pragma unroll
            for (int ma = 0; ma < 2; ma++) {
                uint32_t alog = (uint32_t)((warp_m * 32 + ma * 16 + lrow) * 128
                                           + ks * 32) + lcolb;
                uint32_t ad = st + swz128(alog);
                ldx4(Ahf[ma], ad);
                ldx4(Alf[ma], ad + TILEB);
            }
#pragma unroll
            for (int p = 0; p < 2; p++) {
                uint32_t blog = (uint32_t)((warp_n * 32 + p * 16 + lrow) * 128
                                           + ks * 32) + lcolb;
                uint32_t bd = st + 2 * TILEB + swz128(blog);
                uint32_t q[4];
                ldx4(q, bd);
                Bhf[2 * p][0] = q[0]; Bhf[2 * p][1] = q[2];
                Bhf[2 * p + 1][0] = q[1]; Bhf[2 * p + 1][1] = q[3];
                ldx4(q, bd + TILEB);
                Blf[2 * p][0] = q[0]; Blf[2 * p][1] = q[2];
                Blf[2 * p + 1][0] = q[1]; Blf[2 * p + 1][1] = q[3];
            }
            // term-major bursts
#pragma unroll
            for (int ma = 0; ma < 2; ma++)
#pragma unroll
                for (int na = 0; na < 4; na++)
                    mma16816(acc[ma][na], Ahf[ma], Bhf[na][0], Bhf[na][1]);
#pragma unroll
            for (int ma = 0; ma < 2; ma++)
#pragma unroll
                for (int na = 0; na < 4; na++)
                    mma16816(acc[ma][na], Alf[ma], Bhf[na][0], Bhf[na][1]);
#pragma unroll
            for (int ma = 0; ma < 2; ma++)
#pragma unroll
                for (int na = 0; na < 4; na++)
                    mma16816(acc[ma][na], Ahf[ma], Blf[na][0], Blf[na][1]);
        }
    }
#undef ISSUE

    const int row_b = bm * 128 + warp_m * 32 + (lane >> 2);
    const int col_b = bn * 128 + warp_n * 32 + ((lane & 3) << 1);
#pragma unroll
    for (int ma = 0; ma < 2; ma++) {
#pragma unroll
        for (int na = 0; na < 4; na++) {
            float v0 = acc[ma][na][0], v1 = acc[ma][na][1];
            float v2 = acc[ma][na][2], v3 = acc[ma][na][3];
            if (col_b + na * 8 >= zcol0) {   // fused silu for z columns
                v0 = siluf_(v0); v1 = siluf_(v1);
                v2 = siluf_(v2); v3 = siluf_(v3);
            }
            float* c0 = C + (size_t)(row_b + ma * 16) * N + col_b + na * 8;
            float* c1 = c0 + (size_t)8 * N;
            *(float2*)c0 = make_float2(v0, v1);
            *(float2*)c1 = make_float2(v2, v3);
        }
    }
}

// ============================ elementwise / scan =============================
__global__ __launch_bounds__(256) void conv_silu_kernel(
    const float* __restrict__ cw, const float* __restrict__ cb)
{
    const int d  = blockIdx.x * 256 + threadIdx.x;
    const int b  = blockIdx.z;
    const int t0 = blockIdx.y * 32;
    const float* xin = g_xz + (size_t)b * TLEN * (2 * DI) + d;
    float* xco = g_xconv + ((size_t)b * TLEN + t0) * DI + d;
    __nv_bfloat16* xch = g_xch + ((size_t)b * TLEN + t0) * DI + d;

    const float w0 = cw[d * 4 + 0], w1 = cw[d * 4 + 1];
    const float w2 = cw[d * 4 + 2], w3 = cw[d * 4 + 3];
    const float bias = cb[d];

    float xm3 = (t0 - 3 >= 0) ? xin[(size_t)(t0 - 3) * (2 * DI)] : 0.f;
    float xm2 = (t0 - 2 >= 0) ? xin[(size_t)(t0 - 2) * (2 * DI)] : 0.f;
    float xm1 = (t0 - 1 >= 0) ? xin[(size_t)(t0 - 1) * (2 * DI)] : 0.f;
#pragma unroll 4
    for (int tt = 0; tt < 32; tt++) {
        float xc = xin[(size_t)(t0 + tt) * (2 * DI)];
        float v = w0 * xm3 + w1 * xm2 + w2 * xm1 + w3 * xc + bias;
        float s = siluf_(v);
        xco[(size_t)tt * DI] = s;
        xch[(size_t)tt * DI] = __float2bfloat16_rn(s);
        xm3 = xm2; xm2 = xm1; xm1 = xc;
    }
}

// ---------------------------------------------------------------------------
// Fused B_ssm + dt + alpha. 512 blocks x 16 rows; warps split K 8-ways for
// the B_ssm MMA (SMEM-reduced) then split the dt loop 8-ways.
// ---------------------------------------------------------------------------
__global__ __launch_bounds__(256) void proj_alpha_kernel(const float* __restrict__ dtb)
{
    __shared__ float red[8][32][9];
    __shared__ float rsum[16];
    const int lane = threadIdx.x & 31, wid = threadIdx.x >> 5;
    const int rowbase = blockIdx.x * 16;
    const int r0 = rowbase + (lane >> 2);
    const int k0l = (lane & 3) * 2;
    const int nfr = (lane >> 2);
    const __nv_bfloat16* xr0 = g_xch + (size_t)r0 * DI;
    const __nv_bfloat16* xr8 = xr0 + (size_t)8 * DI;

    float c[2][4];
#pragma unroll
    for (int nt = 0; nt < 2; nt++)
#pragma unroll
        for (int q = 0; q < 4; q++) c[nt][q] = 0.f;

    const int ksbase = wid * 16;
#pragma unroll 4
    for (int ks = 0; ks < 16; ks++) {
        const int k0 = (ksbase + ks) * 16 + k0l;
        uint32_t a[4];
        a[0] = *(const uint32_t*)(xr0 + k0);
        a[1] = *(const uint32_t*)(xr8 + k0);
        a[2] = *(const uint32_t*)(xr0 + k0 + 8);
        a[3] = *(const uint32_t*)(xr8 + k0 + 8);
#pragma unroll
        for (int nt = 0; nt < 2; nt++) {
            const __nv_bfloat16* wn = g_xpwh + (size_t)(nt * 8 + nfr) * DI + k0;
            uint32_t b0 = *(const uint32_t*)(wn);
            uint32_t b1 = *(const uint32_t*)(wn + 8);
            mma16816(c[nt], a, b0, b1);
        }
    }
#pragma unroll
    for (int j = 0; j < 4; j++) {
        red[wid][lane][j]     = c[0][j];
        red[wid][lane][4 + j] = c[1][j];
    }
    if (threadIdx.x < 16) rsum[threadIdx.x] = 0.f;
    __syncthreads();

    float cf[8];
#pragma unroll
    for (int j = 0; j < 8; j++) {
        float s = 0.f;
#pragma unroll
        for (int w = 0; w < 8; w++) s += red[w][lane][j];
        cf[j] = s;
    }
    uint32_t a2[4];
    a2[0] = packbf2(cf[0], cf[1]);
    a2[1] = packbf2(cf[2], cf[3]);
    a2[2] = packbf2(cf[4], cf[5]);
    a2[3] = packbf2(cf[6], cf[7]);

    float sumA = 0.f, sumB = 0.f;
    const int ndbase = wid * 32;
#pragma unroll 4
    for (int nd = ndbase; nd < ndbase + 32; nd++) {
        const int n = nd * 8 + nfr;
        const __nv_bfloat16* wn = g_dtwh + (size_t)n * DS;
        uint32_t b0 = *(const uint32_t*)(wn + k0l);
        uint32_t b1 = *(const uint32_t*)(wn + k0l + 8);
        float cc[4] = {0.f, 0.f, 0.f, 0.f};
        mma16816(cc, a2, b0, b1);
        const int ncx = nd * 8 + k0l;
        float bb0 = dtb[ncx], bb1 = dtb[ncx + 1];
        sumA += softplusf_(cc[0] + bb0) + softplusf_(cc[1] + bb1);
        sumB += softplusf_(cc[2] + bb0) + softplusf_(cc[3] + bb1);
    }
    sumA += __shfl_xor_sync(0xffffffffu, sumA, 1);
    sumA += __shfl_xor_sync(0xffffffffu, sumA, 2);
    sumB += __shfl_xor_sync(0xffffffffu, sumB, 1);
    sumB += __shfl_xor_sync(0xffffffffu, sumB, 2);
    if ((lane & 3) == 0) {
        atomicAdd(&rsum[lane >> 2], sumA);
        atomicAdd(&rsum[8 + (lane >> 2)], sumB);
    }
    __syncthreads();
    if (threadIdx.x < 16)
        g_alpha[rowbase + threadIdx.x] =
            sigmoidf_(rsum[threadIdx.x] * (1.f / (float)DI));
}

__global__ __launch_bounds__(256) void scan1_kernel()
{
    const int d = blockIdx.x * 256 + threadIdx.x;
    const int c = blockIdx.y, b = blockIdx.z;
    const float* xc = g_xconv + ((size_t)b * TLEN + c * CL) * DI + d;
    const float* al = g_alpha + b * TLEN + c * CL;
    float h = 0.f;
#pragma unroll 8
    for (int tt = 0; tt < CL; tt++) {
        float a = al[tt];
        h = fmaf(a, h, (1.f - a) * xc[(size_t)tt * DI]);
    }
    g_S[((size_t)(b * NC + c)) * DI + d] = h;
}

__global__ __launch_bounds__(256) void scan2_kernel()
{
    const int id = blockIdx.x * 256 + threadIdx.x;
    const int b = id / DI, d = id % DI;
    __shared__ float Ps[NC];
    if (threadIdx.x < NC) {
        const float* al = g_alpha + b * TLEN + threadIdx.x * CL;
        float p = 1.f;
#pragma unroll
        for (int tt = 0; tt < CL; tt++) p *= al[tt];
        Ps[threadIdx.x] = p;
    }
    __syncthreads();
    float h = 0.f;
    g_H0[((size_t)(b * NC + 0)) * DI + d] = 0.f;
#pragma unroll 4
    for (int c = 0; c < NC - 1; c++) {
        h = fmaf(Ps[c], h, g_S[((size_t)(b * NC + c)) * DI + d]);
        g_H0[((size_t)(b * NC + c + 1)) * DI + d] = h;
    }
}

// seeded replay; z columns in g_xz already hold silu(z) (fused in in_proj).
__global__ __launch_bounds__(256) void scan3_kernel(const float* __restrict__ Dp)
{
    const int d = blockIdx.x * 256 + threadIdx.x;
    const int c = blockIdx.y, b = blockIdx.z;
    const size_t rbase = (size_t)b * TLEN + c * CL;
    const float* xc = g_xconv + rbase * DI + d;
    const float* zp = g_xz + rbase * (2 * DI) + DI + d;
    const float* al = g_alpha + b * TLEN + c * CL;
    __nv_bfloat16* yh = g_yh + rbase * DI + d;
    __nv_bfloat16* yl = g_yl + rbase * DI + d;
    const float Dv = Dp[d];
    float h = g_H0[((size_t)(b * NC + c)) * DI + d];
#pragma unroll 4
    for (int tt = 0; tt < CL; tt++) {
        float a = al[tt];
        float x = xc[(size_t)tt * DI];
        h = fmaf(a, h, (1.f - a) * x);
        float y = fmaf(h, Dv, x);
        y = y * zp[(size_t)tt * (2 * DI)];   // pre-silu'd gate
        __nv_bfloat16 hh = __float2bfloat16_rn(y);
        yh[(size_t)tt * DI] = hh;
        yl[(size_t)tt * DI] = __float2bfloat16_rn(y - __bfloat162float(hh));
    }
}

// ---------------------------------------------------------------------------
extern "C" void kernel_launch(void* const* d_in, const int* in_sizes, int n_in,
                              void* d_out, int out_size)
{
    const float* x    = (const float*)d_in[0];
    const float* win  = (const float*)d_in[1];
    const float* cw   = (const float*)d_in[2];
    const float* cb   = (const float*)d_in[3];
    const float* xpw  = (const float*)d_in[4];
    const float* dtw  = (const float*)d_in[5];
    const float* dtb  = (const float*)d_in[6];
    const float* Dp   = (const float*)d_in[7];
    const float* wout = (const float*)d_in[8];
    float* out = (float*)d_out;

    float* xz; cudaGetSymbolAddress((void**)&xz, g_xz);
    __nv_bfloat16 *xh, *xl, *wih, *wil, *yh, *yl, *woh, *wol;
    cudaGetSymbolAddress((void**)&xh,  g_xh);
    cudaGetSymbolAddress((void**)&xl,  g_xl);
    cudaGetSymbolAddress((void**)&wih, g_wih);
    cudaGetSymbolAddress((void**)&wil, g_wil);
    cudaGetSymbolAddress((void**)&yh,  g_yh);
    cudaGetSymbolAddress((void**)&yl,  g_yl);
    cudaGetSymbolAddress((void**)&woh, g_woh);
    cudaGetSymbolAddress((void**)&wol, g_wol);

    cudaFuncSetAttribute(gemm3_bf, cudaFuncAttributeMaxDynamicSharedMemorySize,
                         GSMEM);

    // 0) all operand conversions in one launch
    cvt_all_kernel<<<(CV_N4 + 255) / 256, 256>>>(x, win, wout, xpw, dtw);
    // 1) in_proj (z-half gets fused silu)
    gemm3_bf<<<dim3((2 * DI) / 128, MROWS / 128), 512, GSMEM>>>(
        xh, xl, wih, wil, xz, 2 * DI, DM, DI);
    // 2) depthwise causal conv + SiLU
    conv_silu_kernel<<<dim3(DI / 256, TLEN / 32, BSZ), 256>>>(cw, cb);
    // 3) fused B_ssm + dt + alpha
    proj_alpha_kernel<<<MROWS / 16, 256>>>(dtb);
    // 4) chunked scan
    scan1_kernel<<<dim3(DI / 256, NC, BSZ), 256>>>();
    scan2_kernel<<<MROWS / 256, 256>>>();
    scan3_kernel<<<dim3(DI / 256, NC, BSZ), 256>>>(Dp);
    // 5) out_proj (no silu)
    gemm3_bf<<<dim3(DM / 128, MROWS / 128), 512, GSMEM>>>(
        yh, yl, woh, wol, out, DM, DI, 1 << 30);
}

// round 15
// speedup vs baseline: 1.2531x; 1.0028x over previous
#include <cuda_runtime.h>
#include <cuda_bf16.h>
#include <math.h>
#include <stdint.h>

// Problem constants
#define BSZ 4
#define TLEN 2048
#define DM 1024
#define DI 2048
#define DS 16
#define DC 4
#define MROWS (BSZ * TLEN)        // 8192
#define NC 64                      // scan chunks
#define CL 32                      // chunk length

// -------- scratch (device globals) --------
__device__ float g_xz[(size_t)MROWS * 2 * DI];
__device__ float g_xconv[(size_t)MROWS * DI];
__device__ float g_alpha[MROWS];
__device__ float g_S[(size_t)BSZ * NC * DI];
__device__ float g_H0[(size_t)BSZ * NC * DI];
__device__ __nv_bfloat16 g_xh[(size_t)MROWS * DM],  g_xl[(size_t)MROWS * DM];
__device__ __nv_bfloat16 g_wih[(size_t)2 * DI * DM], g_wil[(size_t)2 * DI * DM];
__device__ __nv_bfloat16 g_yh[(size_t)MROWS * DI],  g_yl[(size_t)MROWS * DI];
__device__ __nv_bfloat16 g_woh[(size_t)DM * DI],    g_wol[(size_t)DM * DI];
__device__ __nv_bfloat16 g_xch[(size_t)MROWS * DI];
__device__ __nv_bfloat16 g_xpwh[(size_t)DS * DI];
__device__ __nv_bfloat16 g_dtwh[(size_t)DI * DS];

// ============================ helpers =======================================
__device__ __forceinline__ uint32_t smem_u32(const void* p) {
    uint32_t a;
    asm("{ .reg .u64 t; cvta.to.shared.u64 t, %1; cvt.u32.u64 %0, t; }"
        : "=r"(a) : "l"(p));
    return a;
}
__device__ __forceinline__ void ldx4(uint32_t* r, uint32_t addr) {
    asm volatile("ldmatrix.sync.aligned.m8n8.x4.shared.b16 {%0,%1,%2,%3}, [%4];"
        : "=r"(r[0]), "=r"(r[1]), "=r"(r[2]), "=r"(r[3]) : "r"(addr));
}
__device__ __forceinline__ void mma16816(float* c, const uint32_t* a,
                                         uint32_t b0, uint32_t b1) {
    asm volatile(
        "mma.sync.aligned.m16n8k16.row.col.f32.bf16.bf16.f32 "
        "{%0,%1,%2,%3}, {%4,%5,%6,%7}, {%8,%9}, {%0,%1,%2,%3};"
        : "+f"(c[0]), "+f"(c[1]), "+f"(c[2]), "+f"(c[3])
        : "r"(a[0]), "r"(a[1]), "r"(a[2]), "r"(a[3]), "r"(b0), "r"(b1));
}
__device__ __forceinline__ void cp16(uint32_t s, const void* g) {
    asm volatile("cp.async.cg.shared.global [%0], [%1], 16;"
        :: "r"(s), "l"(g) : "memory");
}
__device__ __forceinline__ float sigmoidf_(float v) { return 1.f / (1.f + __expf(-v)); }
__device__ __forceinline__ float siluf_(float v)    { return v * sigmoidf_(v); }
__device__ __forceinline__ float softplusf_(float v) {
    return (v > 20.f) ? v : __logf(1.f + __expf(v));
}
__device__ __forceinline__ uint32_t packbf2(float a, float b) {
    __nv_bfloat162 t = __floats2bfloat162_rn(a, b);
    return *(uint32_t*)&t;
}
__device__ __forceinline__ uint32_t swz128(uint32_t o) {
    return o ^ ((o >> 3) & 0x70);
}

// ---------------------------------------------------------------------------
// Merged operand conversion: x/win/wout split hi+lo; xpw/dtw hi only.
// ---------------------------------------------------------------------------
#define CV_N0 (MROWS * DM / 4)
#define CV_N1 (CV_N0 + 2 * DI * DM / 4)
#define CV_N2 (CV_N1 + DM * DI / 4)
#define CV_N3 (CV_N2 + DS * DI / 4)
#define CV_N4 (CV_N3 + DI * DS / 4)

__global__ __launch_bounds__(256) void cvt_all_kernel(
    const float* __restrict__ x, const float* __restrict__ win,
    const float* __restrict__ wout, const float* __restrict__ xpw,
    const float* __restrict__ dtw)
{
    int i = blockIdx.x * 256 + threadIdx.x;
    if (i >= CV_N4) return;
    const float* src; __nv_bfloat16 *hi, *lo; int j; bool split = true;
    if (i < CV_N0)      { j = i;         src = x;    hi = g_xh;  lo = g_xl;  }
    else if (i < CV_N1) { j = i - CV_N0; src = win;  hi = g_wih; lo = g_wil; }
    else if (i < CV_N2) { j = i - CV_N1; src = wout; hi = g_woh; lo = g_wol; }
    else if (i < CV_N3) { j = i - CV_N2; src = xpw;  hi = g_xpwh; lo = 0; split = false; }
    else                { j = i - CV_N3; src = dtw;  hi = g_dtwh; lo = 0; split = false; }
    float4 v = ((const float4*)src)[j];
    float vv[4] = {v.x, v.y, v.z, v.w};
    __nv_bfloat16 h[4], l[4];
#pragma unroll
    for (int k = 0; k < 4; k++) {
        h[k] = __float2bfloat16_rn(vv[k]);
        l[k] = __float2bfloat16_rn(vv[k] - __bfloat162float(h[k]));
    }
    ((uint2*)hi)[j] = *(uint2*)h;
    if (split) ((uint2*)lo)[j] = *(uint2*)l;
}

// ---------------------------------------------------------------------------
// Persistent split-bf16 NT GEMM via mma.sync. CTA 128x128, 512 threads
// (4x4 warps, 32x32 warp tiles), KC=64, 3-stage cp.async, term-major order.
// Grid = 152 persistent CTAs looping over tiles (kills wave-tail waste).
// Optional fused silu for columns >= zcol0 (in_proj z-half).
// ---------------------------------------------------------------------------
#define KC    64
#define TILEB (128 * 128)          // 16384
#define STGB  (4 * TILEB)          // 65536
#define NSTG  3
#define GSMEM (NSTG * STGB)        // 196608
#define NPERS 152

__global__ void __launch_bounds__(512, 1) gemm3_bf(
    const __nv_bfloat16* __restrict__ Ah_, const __nv_bfloat16* __restrict__ Al_,
    const __nv_bfloat16* __restrict__ Bh_, const __nv_bfloat16* __restrict__ Bl_,
    float* __restrict__ C, int N, int K, int zcol0, int nbn, int ntiles)
{
    extern __shared__ char smem[];
    const uint32_t sb = smem_u32(smem);
    const int tid = threadIdx.x, lane = tid & 31, wid = tid >> 5;
    const int warp_m = wid >> 2, warp_n = wid & 3;   // 4 x 4 warps

    const int crow = tid >> 2, cu = tid & 3;
    const uint32_t d0 = swz128((uint32_t)(crow * 128 + cu * 16));
    const uint32_t d1 = swz128((uint32_t)(crow * 128 + (cu + 4) * 16));
    const uint32_t lrow = lane & 15, lcolb = (lane >> 4) * 16;
    const int nch = K / KC;

    for (int tile = blockIdx.x; tile < ntiles; tile += gridDim.x) {
        const int bm = tile / nbn, bn = tile % nbn;
        const size_t a_src = (size_t)(bm * 128 + crow) * K + cu * 8;
        const size_t b_src = (size_t)(bn * 128 + crow) * K + cu * 8;

        float acc[2][4][4];
#pragma unroll
        for (int i = 0; i < 2; i++)
#pragma unroll
            for (int j = 0; j < 4; j++)
#pragma unroll
                for (int q = 0; q < 4; q++) acc[i][j][q] = 0.f;

#define ISSUE(ch, stg) do { \
        uint32_t dst = sb + (uint32_t)(stg) * STGB; \
        size_t koff = (size_t)(ch) * KC; \
        cp16(dst + 0 * TILEB + d0, Ah_ + a_src + koff); \
        cp16(dst + 0 * TILEB + d1, Ah_ + a_src + koff + 32); \
        cp16(dst + 1 * TILEB + d0, Al_ + a_src + koff); \
        cp16(dst + 1 * TILEB + d1, Al_ + a_src + koff + 32); \
        cp16(dst + 2 * TILEB + d0, Bh_ + b_src + koff); \
        cp16(dst + 2 * TILEB + d1, Bh_ + b_src + koff + 32); \
        cp16(dst + 3 * TILEB + d0, Bl_ + b_src + koff); \
        cp16(dst + 3 * TILEB + d1, Bl_ + b_src + koff + 32); \
        asm volatile("cp.async.commit_group;" ::: "memory"); \
    } while (0)

        ISSUE(0, 0);
        ISSUE(1, 1);

        int cs = 0, is = 2;
        for (int ch = 0; ch < nch; ch++) {
            if (ch + 1 < nch)
                asm volatile("cp.async.wait_group 1;" ::: "memory");
            else
                asm volatile("cp.async.wait_group 0;" ::: "memory");
            __syncthreads();
            if (ch + 2 < nch) {
                ISSUE(ch + 2, is);
                is = (is == 2) ? 0 : is + 1;
            }

            const uint32_t st = sb + (uint32_t)cs * STGB;
            cs = (cs == 2) ? 0 : cs + 1;
#pragma unroll
            for (int ks = 0; ks < 4; ks++) {
                uint32_t Ahf[2][4], Alf[2][4], Bhf[4][2], Blf[4][2];
#pragma unroll
                for (int ma = 0; ma < 2; ma++) {
                    uint32_t alog = (uint32_t)((warp_m * 32 + ma * 16 + lrow) * 128
                                               + ks * 32) + lcolb;
                    uint32_t ad = st + swz128(alog);
                    ldx4(Ahf[ma], ad);
                    ldx4(Alf[ma], ad + TILEB);
                }
#pragma unroll
                for (int p = 0; p < 2; p++) {
                    uint32_t blog = (uint32_t)((warp_n * 32 + p * 16 + lrow) * 128
                                               + ks * 32) + lcolb;
                    uint32_t bd = st + 2 * TILEB + swz128(blog);
                    uint32_t q[4];
                    ldx4(q, bd);
                    Bhf[2 * p][0] = q[0]; Bhf[2 * p][1] = q[2];
                    Bhf[2 * p + 1][0] = q[1]; Bhf[2 * p + 1][1] = q[3];
                    ldx4(q, bd + TILEB);
                    Blf[2 * p][0] = q[0]; Blf[2 * p][1] = q[2];
                    Blf[2 * p + 1][0] = q[1]; Blf[2 * p + 1][1] = q[3];
                }
#pragma unroll
                for (int ma = 0; ma < 2; ma++)
#pragma unroll
                    for (int na = 0; na < 4; na++)
                        mma16816(acc[ma][na], Ahf[ma], Bhf[na][0], Bhf[na][1]);
#pragma unroll
                for (int ma = 0; ma < 2; ma++)
#pragma unroll
                    for (int na = 0; na < 4; na++)
                        mma16816(acc[ma][na], Alf[ma], Bhf[na][0], Bhf[na][1]);
#pragma unroll
                for (int ma = 0; ma < 2; ma++)
#pragma unroll
                    for (int na = 0; na < 4; na++)
                        mma16816(acc[ma][na], Ahf[ma], Blf[na][0], Blf[na][1]);
            }
        }
#undef ISSUE

        const int row_b = bm * 128 + warp_m * 32 + (lane >> 2);
        const int col_b = bn * 128 + warp_n * 32 + ((lane & 3) << 1);
#pragma unroll
        for (int ma = 0; ma < 2; ma++) {
#pragma unroll
            for (int na = 0; na < 4; na++) {
                float v0 = acc[ma][na][0], v1 = acc[ma][na][1];
                float v2 = acc[ma][na][2], v3 = acc[ma][na][3];
                if (col_b + na * 8 >= zcol0) {
                    v0 = siluf_(v0); v1 = siluf_(v1);
                    v2 = siluf_(v2); v3 = siluf_(v3);
                }
                float* c0 = C + (size_t)(row_b + ma * 16) * N + col_b + na * 8;
                float* c1 = c0 + (size_t)8 * N;
                *(float2*)c0 = make_float2(v0, v1);
                *(float2*)c1 = make_float2(v2, v3);
            }
        }
        __syncthreads();   // smem stages reusable by next tile
    }
}

// ============================ elementwise / scan =============================
__global__ __launch_bounds__(256) void conv_silu_kernel(
    const float* __restrict__ cw, const float* __restrict__ cb)
{
    const int d  = blockIdx.x * 256 + threadIdx.x;
    const int b  = blockIdx.z;
    const int t0 = blockIdx.y * 32;
    const float* xin = g_xz + (size_t)b * TLEN * (2 * DI) + d;
    float* xco = g_xconv + ((size_t)b * TLEN + t0) * DI + d;
    __nv_bfloat16* xch = g_xch + ((size_t)b * TLEN + t0) * DI + d;

    const float w0 = cw[d * 4 + 0], w1 = cw[d * 4 + 1];
    const float w2 = cw[d * 4 + 2], w3 = cw[d * 4 + 3];
    const float bias = cb[d];

    float xm3 = (t0 - 3 >= 0) ? xin[(size_t)(t0 - 3) * (2 * DI)] : 0.f;
    float xm2 = (t0 - 2 >= 0) ? xin[(size_t)(t0 - 2) * (2 * DI)] : 0.f;
    float xm1 = (t0 - 1 >= 0) ? xin[(size_t)(t0 - 1) * (2 * DI)] : 0.f;
#pragma unroll 4
    for (int tt = 0; tt < 32; tt++) {
        float xc = xin[(size_t)(t0 + tt) * (2 * DI)];
        float v = w0 * xm3 + w1 * xm2 + w2 * xm1 + w3 * xc + bias;
        float s = siluf_(v);
        xco[(size_t)tt * DI] = s;
        xch[(size_t)tt * DI] = __float2bfloat16_rn(s);
        xm3 = xm2; xm2 = xm1; xm1 = xc;
    }
}

// ---------------------------------------------------------------------------
// Fused B_ssm + dt + alpha. 512 blocks x 16 rows; warps split K 8-ways for
// the B_ssm MMA (SMEM-reduced) then split the dt loop 8-ways.
// ---------------------------------------------------------------------------
__global__ __launch_bounds__(256) void proj_alpha_kernel(const float* __restrict__ dtb)
{
    __shared__ float red[8][32][9];
    __shared__ float rsum[16];
    const int lane = threadIdx.x & 31, wid = threadIdx.x >> 5;
    const int rowbase = blockIdx.x * 16;
    const int r0 = rowbase + (lane >> 2);
    const int k0l = (lane & 3) * 2;
    const int nfr = (lane >> 2);
    const __nv_bfloat16* xr0 = g_xch + (size_t)r0 * DI;
    const __nv_bfloat16* xr8 = xr0 + (size_t)8 * DI;

    float c[2][4];
#pragma unroll
    for (int nt = 0; nt < 2; nt++)
#pragma unroll
        for (int q = 0; q < 4; q++) c[nt][q] = 0.f;

    const int ksbase = wid * 16;
#pragma unroll 4
    for (int ks = 0; ks < 16; ks++) {
        const int k0 = (ksbase + ks) * 16 + k0l;
        uint32_t a[4];
        a[0] = *(const uint32_t*)(xr0 + k0);
        a[1] = *(const uint32_t*)(xr8 + k0);
        a[2] = *(const uint32_t*)(xr0 + k0 + 8);
        a[3] = *(const uint32_t*)(xr8 + k0 + 8);
#pragma unroll
        for (int nt = 0; nt < 2; nt++) {
            const __nv_bfloat16* wn = g_xpwh + (size_t)(nt * 8 + nfr) * DI + k0;
            uint32_t b0 = *(const uint32_t*)(wn);
            uint32_t b1 = *(const uint32_t*)(wn + 8);
            mma16816(c[nt], a, b0, b1);
        }
    }
#pragma unroll
    for (int j = 0; j < 4; j++) {
        red[wid][lane][j]     = c[0][j];
        red[wid][lane][4 + j] = c[1][j];
    }
    if (threadIdx.x < 16) rsum[threadIdx.x] = 0.f;
    __syncthreads();

    float cf[8];
#pragma unroll
    for (int j = 0; j < 8; j++) {
        float s = 0.f;
#pragma unroll
        for (int w = 0; w < 8; w++) s += red[w][lane][j];
        cf[j] = s;
    }
    uint32_t a2[4];
    a2[0] = packbf2(cf[0], cf[1]);
    a2[1] = packbf2(cf[2], cf[3]);
    a2[2] = packbf2(cf[4], cf[5]);
    a2[3] = packbf2(cf[6], cf[7]);

    float sumA = 0.f, sumB = 0.f;
    const int ndbase = wid * 32;
#pragma unroll 4
    for (int nd = ndbase; nd < ndbase + 32; nd++) {
        const int n = nd * 8 + nfr;
        const __nv_bfloat16* wn = g_dtwh + (size_t)n * DS;
        uint32_t b0 = *(const uint32_t*)(wn + k0l);
        uint32_t b1 = *(const uint32_t*)(wn + k0l + 8);
        float cc[4] = {0.f, 0.f, 0.f, 0.f};
        mma16816(cc, a2, b0, b1);
        const int ncx = nd * 8 + k0l;
        float bb0 = dtb[ncx], bb1 = dtb[ncx + 1];
        sumA += softplusf_(cc[0] + bb0) + softplusf_(cc[1] + bb1);
        sumB += softplusf_(cc[2] + bb0) + softplusf_(cc[3] + bb1);
    }
    sumA += __shfl_xor_sync(0xffffffffu, sumA, 1);
    sumA += __shfl_xor_sync(0xffffffffu, sumA, 2);
    sumB += __shfl_xor_sync(0xffffffffu, sumB, 1);
    sumB += __shfl_xor_sync(0xffffffffu, sumB, 2);
    if ((lane & 3) == 0) {
        atomicAdd(&rsum[lane >> 2], sumA);
        atomicAdd(&rsum[8 + (lane >> 2)], sumB);
    }
    __syncthreads();
    if (threadIdx.x < 16)
        g_alpha[rowbase + threadIdx.x] =
            sigmoidf_(rsum[threadIdx.x] * (1.f / (float)DI));
}

__global__ __launch_bounds__(256) void scan1_kernel()
{
    const int d = blockIdx.x * 256 + threadIdx.x;
    const int c = blockIdx.y, b = blockIdx.z;
    const float* xc = g_xconv + ((size_t)b * TLEN + c * CL) * DI + d;
    const float* al = g_alpha + b * TLEN + c * CL;
    float h = 0.f;
#pragma unroll 8
    for (int tt = 0; tt < CL; tt++) {
        float a = al[tt];
        h = fmaf(a, h, (1.f - a) * xc[(size_t)tt * DI]);
    }
    g_S[((size_t)(b * NC + c)) * DI + d] = h;
}

__global__ __launch_bounds__(256) void scan2_kernel()
{
    const int id = blockIdx.x * 256 + threadIdx.x;
    const int b = id / DI, d = id % DI;
    __shared__ float Ps[NC];
    if (threadIdx.x < NC) {
        const float* al = g_alpha + b * TLEN + threadIdx.x * CL;
        float p = 1.f;
#pragma unroll
        for (int tt = 0; tt < CL; tt++) p *= al[tt];
        Ps[threadIdx.x] = p;
    }
    __syncthreads();
    float h = 0.f;
    g_H0[((size_t)(b * NC + 0)) * DI + d] = 0.f;
#pragma unroll 4
    for (int c = 0; c < NC - 1; c++) {
        h = fmaf(Ps[c], h, g_S[((size_t)(b * NC + c)) * DI + d]);
        g_H0[((size_t)(b * NC + c + 1)) * DI + d] = h;
    }
}

// seeded replay; z columns in g_xz already hold silu(z) (fused in in_proj).
__global__ __launch_bounds__(256) void scan3_kernel(const float* __restrict__ Dp)
{
    const int d = blockIdx.x * 256 + threadIdx.x;
    const int c = blockIdx.y, b = blockIdx.z;
    const size_t rbase = (size_t)b * TLEN + c * CL;
    const float* xc = g_xconv + rbase * DI + d;
    const float* zp = g_xz + rbase * (2 * DI) + DI + d;
    const float* al = g_alpha + b * TLEN + c * CL;
    __nv_bfloat16* yh = g_yh + rbase * DI + d;
    __nv_bfloat16* yl = g_yl + rbase * DI + d;
    const float Dv = Dp[d];
    float h = g_H0[((size_t)(b * NC + c)) * DI + d];
#pragma unroll 4
    for (int tt = 0; tt < CL; tt++) {
        float a = al[tt];
        float x = xc[(size_t)tt * DI];
        h = fmaf(a, h, (1.f - a) * x);
        float y = fmaf(h, Dv, x);
        y = y * zp[(size_t)tt * (2 * DI)];
        __nv_bfloat16 hh = __float2bfloat16_rn(y);
        yh[(size_t)tt * DI] = hh;
        yl[(size_t)tt * DI] = __float2bfloat16_rn(y - __bfloat162float(hh));
    }
}

// ---------------------------------------------------------------------------
extern "C" void kernel_launch(void* const* d_in, const int* in_sizes, int n_in,
                              void* d_out, int out_size)
{
    const float* x    = (const float*)d_in[0];
    const float* win  = (const float*)d_in[1];
    const float* cw   = (const float*)d_in[2];
    const float* cb   = (const float*)d_in[3];
    const float* xpw  = (const float*)d_in[4];
    const float* dtw  = (const float*)d_in[5];
    const float* dtb  = (const float*)d_in[6];
    const float* Dp   = (const float*)d_in[7];
    const float* wout = (const float*)d_in[8];
    float* out = (float*)d_out;

    float* xz; cudaGetSymbolAddress((void**)&xz, g_xz);
    __nv_bfloat16 *xh, *xl, *wih, *wil, *yh, *yl, *woh, *wol;
    cudaGetSymbolAddress((void**)&xh,  g_xh);
    cudaGetSymbolAddress((void**)&xl,  g_xl);
    cudaGetSymbolAddress((void**)&wih, g_wih);
    cudaGetSymbolAddress((void**)&wil, g_wil);
    cudaGetSymbolAddress((void**)&yh,  g_yh);
    cudaGetSymbolAddress((void**)&yl,  g_yl);
    cudaGetSymbolAddress((void**)&woh, g_woh);
    cudaGetSymbolAddress((void**)&wol, g_wol);

    cudaFuncSetAttribute(gemm3_bf, cudaFuncAttributeMaxDynamicSharedMemorySize,
                         GSMEM);

    // 0) all operand conversions in one launch
    cvt_all_kernel<<<(CV_N4 + 255) / 256, 256>>>(x, win, wout, xpw, dtw);
    // 1) in_proj (persistent; z-half gets fused silu): 64x32 = 2048 tiles
    gemm3_bf<<<NPERS, 512, GSMEM>>>(
        xh, xl, wih, wil, xz, 2 * DI, DM, DI,
        (2 * DI) / 128, (MROWS / 128) * ((2 * DI) / 128));
    // 2) depthwise causal conv + SiLU
    conv_silu_kernel<<<dim3(DI / 256, TLEN / 32, BSZ), 256>>>(cw, cb);
    // 3) fused B_ssm + dt + alpha
    proj_alpha_kernel<<<MROWS / 16, 256>>>(dtb);
    // 4) chunked scan
    scan1_kernel<<<dim3(DI / 256, NC, BSZ), 256>>>();
    scan2_kernel<<<MROWS / 256, 256>>>();
    scan3_kernel<<<dim3(DI / 256, NC, BSZ), 256>>>(Dp);
    // 5) out_proj (persistent; no silu): 64x8 = 512 tiles
    gemm3_bf<<<NPERS, 512, GSMEM>>>(
        yh, yl, woh, wol, out, DM, DI, 1 << 30,
        DM / 128, (MROWS / 128) * (DM / 128));
}

// round 16
// speedup vs baseline: 1.2675x; 1.0115x over previous
#include <cuda_runtime.h>
#include <cuda_bf16.h>
#include <math.h>
#include <stdint.h>

// Problem constants
#define BSZ 4
#define TLEN 2048
#define DM 1024
#define DI 2048
#define DS 16
#define DC 4
#define MROWS (BSZ * TLEN)        // 8192
#define NC 64                      // scan chunks
#define CL 32                      // chunk length

// -------- scratch (device globals) --------
__device__ float g_xz[(size_t)MROWS * 2 * DI];
__device__ float g_xconv[(size_t)MROWS * DI];
__device__ float g_alpha[MROWS];
__device__ float g_S[(size_t)BSZ * NC * DI];
__device__ float g_H0[(size_t)BSZ * NC * DI];
__device__ __nv_bfloat16 g_xh[(size_t)MROWS * DM],  g_xl[(size_t)MROWS * DM];
__device__ __nv_bfloat16 g_wih[(size_t)2 * DI * DM], g_wil[(size_t)2 * DI * DM];
__device__ __nv_bfloat16 g_yh[(size_t)MROWS * DI],  g_yl[(size_t)MROWS * DI];
__device__ __nv_bfloat16 g_woh[(size_t)DM * DI],    g_wol[(size_t)DM * DI];
__device__ __nv_bfloat16 g_xch[(size_t)MROWS * DI];
__device__ __nv_bfloat16 g_xpwh[(size_t)DS * DI];
__device__ __nv_bfloat16 g_dtwh[(size_t)DI * DS];

// ============================ helpers =======================================
__device__ __forceinline__ uint32_t smem_u32(const void* p) {
    uint32_t a;
    asm("{ .reg .u64 t; cvta.to.shared.u64 t, %1; cvt.u32.u64 %0, t; }"
        : "=r"(a) : "l"(p));
    return a;
}
__device__ __forceinline__ void ldx4(uint32_t* r, uint32_t addr) {
    asm volatile("ldmatrix.sync.aligned.m8n8.x4.shared.b16 {%0,%1,%2,%3}, [%4];"
        : "=r"(r[0]), "=r"(r[1]), "=r"(r[2]), "=r"(r[3]) : "r"(addr));
}
__device__ __forceinline__ void mma16816(float* c, const uint32_t* a,
                                         uint32_t b0, uint32_t b1) {
    asm volatile(
        "mma.sync.aligned.m16n8k16.row.col.f32.bf16.bf16.f32 "
        "{%0,%1,%2,%3}, {%4,%5,%6,%7}, {%8,%9}, {%0,%1,%2,%3};"
        : "+f"(c[0]), "+f"(c[1]), "+f"(c[2]), "+f"(c[3])
        : "r"(a[0]), "r"(a[1]), "r"(a[2]), "r"(a[3]), "r"(b0), "r"(b1));
}
__device__ __forceinline__ void cp16(uint32_t s, const void* g) {
    asm volatile("cp.async.cg.shared.global [%0], [%1], 16;"
        :: "r"(s), "l"(g) : "memory");
}
__device__ __forceinline__ float sigmoidf_(float v) { return 1.f / (1.f + __expf(-v)); }
__device__ __forceinline__ float siluf_(float v)    { return v * sigmoidf_(v); }
__device__ __forceinline__ float softplusf_(float v) {
    return (v > 20.f) ? v : __logf(1.f + __expf(v));
}
__device__ __forceinline__ uint32_t packbf2(float a, float b) {
    __nv_bfloat162 t = __floats2bfloat162_rn(a, b);
    return *(uint32_t*)&t;
}
__device__ __forceinline__ uint32_t swz128(uint32_t o) {
    return o ^ ((o >> 3) & 0x70);
}

// ---------------------------------------------------------------------------
// Merged operand conversion: x/win/wout split hi+lo; xpw/dtw hi only.
// ---------------------------------------------------------------------------
#define CV_N0 (MROWS * DM / 4)
#define CV_N1 (CV_N0 + 2 * DI * DM / 4)
#define CV_N2 (CV_N1 + DM * DI / 4)
#define CV_N3 (CV_N2 + DS * DI / 4)
#define CV_N4 (CV_N3 + DI * DS / 4)

__global__ __launch_bounds__(256) void cvt_all_kernel(
    const float* __restrict__ x, const float* __restrict__ win,
    const float* __restrict__ wout, const float* __restrict__ xpw,
    const float* __restrict__ dtw)
{
    int i = blockIdx.x * 256 + threadIdx.x;
    if (i >= CV_N4) return;
    const float* src; __nv_bfloat16 *hi, *lo; int j; bool split = true;
    if (i < CV_N0)      { j = i;         src = x;    hi = g_xh;  lo = g_xl;  }
    else if (i < CV_N1) { j = i - CV_N0; src = win;  hi = g_wih; lo = g_wil; }
    else if (i < CV_N2) { j = i - CV_N1; src = wout; hi = g_woh; lo = g_wol; }
    else if (i < CV_N3) { j = i - CV_N2; src = xpw;  hi = g_xpwh; lo = 0; split = false; }
    else                { j = i - CV_N3; src = dtw;  hi = g_dtwh; lo = 0; split = false; }
    float4 v = ((const float4*)src)[j];
    float vv[4] = {v.x, v.y, v.z, v.w};
    __nv_bfloat16 h[4], l[4];
#pragma unroll
    for (int k = 0; k < 4; k++) {
        h[k] = __float2bfloat16_rn(vv[k]);
        l[k] = __float2bfloat16_rn(vv[k] - __bfloat162float(h[k]));
    }
    ((uint2*)hi)[j] = *(uint2*)h;
    if (split) ((uint2*)lo)[j] = *(uint2*)l;
}

// ---------------------------------------------------------------------------
// Split-bf16 NT GEMM via mma.sync. CTA 128x128, 512 threads (4x4 warps,
// 32x32 warp tiles), KC=64, 3-stage cp.async, term-major order. Tile-strided
// persistent loop; bn_off selects a column band (for in_proj x/z halves).
// silu fused for global columns >= zcol0.
// ---------------------------------------------------------------------------
#define KC    64
#define TILEB (128 * 128)          // 16384
#define STGB  (4 * TILEB)          // 65536
#define NSTG  3
#define GSMEM (NSTG * STGB)        // 196608
#define NPERS 152

__global__ void __launch_bounds__(512, 1) gemm3_bf(
    const __nv_bfloat16* __restrict__ Ah_, const __nv_bfloat16* __restrict__ Al_,
    const __nv_bfloat16* __restrict__ Bh_, const __nv_bfloat16* __restrict__ Bl_,
    float* __restrict__ C, int N, int K, int zcol0, int nbn, int bn_off, int ntiles)
{
    extern __shared__ char smem[];
    const uint32_t sb = smem_u32(smem);
    const int tid = threadIdx.x, lane = tid & 31, wid = tid >> 5;
    const int warp_m = wid >> 2, warp_n = wid & 3;   // 4 x 4 warps

    const int crow = tid >> 2, cu = tid & 3;
    const uint32_t d0 = swz128((uint32_t)(crow * 128 + cu * 16));
    const uint32_t d1 = swz128((uint32_t)(crow * 128 + (cu + 4) * 16));
    const uint32_t lrow = lane & 15, lcolb = (lane >> 4) * 16;
    const int nch = K / KC;

    for (int tile = blockIdx.x; tile < ntiles; tile += gridDim.x) {
        const int bm = tile / nbn, bn = tile % nbn + bn_off;
        const size_t a_src = (size_t)(bm * 128 + crow) * K + cu * 8;
        const size_t b_src = (size_t)(bn * 128 + crow) * K + cu * 8;

        float acc[2][4][4];
#pragma unroll
        for (int i = 0; i < 2; i++)
#pragma unroll
            for (int j = 0; j < 4; j++)
#pragma unroll
                for (int q = 0; q < 4; q++) acc[i][j][q] = 0.f;

#define ISSUE(ch, stg) do { \
        uint32_t dst = sb + (uint32_t)(stg) * STGB; \
        size_t koff = (size_t)(ch) * KC; \
        cp16(dst + 0 * TILEB + d0, Ah_ + a_src + koff); \
        cp16(dst + 0 * TILEB + d1, Ah_ + a_src + koff + 32); \
        cp16(dst + 1 * TILEB + d0, Al_ + a_src + koff); \
        cp16(dst + 1 * TILEB + d1, Al_ + a_src + koff + 32); \
        cp16(dst + 2 * TILEB + d0, Bh_ + b_src + koff); \
        cp16(dst + 2 * TILEB + d1, Bh_ + b_src + koff + 32); \
        cp16(dst + 3 * TILEB + d0, Bl_ + b_src + koff); \
        cp16(dst + 3 * TILEB + d1, Bl_ + b_src + koff + 32); \
        asm volatile("cp.async.commit_group;" ::: "memory"); \
    } while (0)

        ISSUE(0, 0);
        ISSUE(1, 1);

        int cs = 0, is = 2;
        for (int ch = 0; ch < nch; ch++) {
            if (ch + 1 < nch)
                asm volatile("cp.async.wait_group 1;" ::: "memory");
            else
                asm volatile("cp.async.wait_group 0;" ::: "memory");
            __syncthreads();
            if (ch + 2 < nch) {
                ISSUE(ch + 2, is);
                is = (is == 2) ? 0 : is + 1;
            }

            const uint32_t st = sb + (uint32_t)cs * STGB;
            cs = (cs == 2) ? 0 : cs + 1;
#pragma unroll
            for (int ks = 0; ks < 4; ks++) {
                uint32_t Ahf[2][4], Alf[2][4], Bhf[4][2], Blf[4][2];
#pragma unroll
                for (int ma = 0; ma < 2; ma++) {
                    uint32_t alog = (uint32_t)((warp_m * 32 + ma * 16 + lrow) * 128
                                               + ks * 32) + lcolb;
                    uint32_t ad = st + swz128(alog);
                    ldx4(Ahf[ma], ad);
                    ldx4(Alf[ma], ad + TILEB);
                }
#pragma unroll
                for (int p = 0; p < 2; p++) {
                    uint32_t blog = (uint32_t)((warp_n * 32 + p * 16 + lrow) * 128
                                               + ks * 32) + lcolb;
                    uint32_t bd = st + 2 * TILEB + swz128(blog);
                    uint32_t q[4];
                    ldx4(q, bd);
                    Bhf[2 * p][0] = q[0]; Bhf[2 * p][1] = q[2];
                    Bhf[2 * p + 1][0] = q[1]; Bhf[2 * p + 1][1] = q[3];
                    ldx4(q, bd + TILEB);
                    Blf[2 * p][0] = q[0]; Blf[2 * p][1] = q[2];
                    Blf[2 * p + 1][0] = q[1]; Blf[2 * p + 1][1] = q[3];
                }
#pragma unroll
                for (int ma = 0; ma < 2; ma++)
#pragma unroll
                    for (int na = 0; na < 4; na++)
                        mma16816(acc[ma][na], Ahf[ma], Bhf[na][0], Bhf[na][1]);
#pragma unroll
                for (int ma = 0; ma < 2; ma++)
#pragma unroll
                    for (int na = 0; na < 4; na++)
                        mma16816(acc[ma][na], Alf[ma], Bhf[na][0], Bhf[na][1]);
#pragma unroll
                for (int ma = 0; ma < 2; ma++)
#pragma unroll
                    for (int na = 0; na < 4; na++)
                        mma16816(acc[ma][na], Ahf[ma], Blf[na][0], Blf[na][1]);
            }
        }
#undef ISSUE

        const int row_b = bm * 128 + warp_m * 32 + (lane >> 2);
        const int col_b = bn * 128 + warp_n * 32 + ((lane & 3) << 1);
#pragma unroll
        for (int ma = 0; ma < 2; ma++) {
#pragma unroll
            for (int na = 0; na < 4; na++) {
                float v0 = acc[ma][na][0], v1 = acc[ma][na][1];
                float v2 = acc[ma][na][2], v3 = acc[ma][na][3];
                if (col_b + na * 8 >= zcol0) {
                    v0 = siluf_(v0); v1 = siluf_(v1);
                    v2 = siluf_(v2); v3 = siluf_(v3);
                }
                float* c0 = C + (size_t)(row_b + ma * 16) * N + col_b + na * 8;
                float* c1 = c0 + (size_t)8 * N;
                *(float2*)c0 = make_float2(v0, v1);
                *(float2*)c1 = make_float2(v2, v3);
            }
        }
        __syncthreads();   // smem stages reusable by next tile
    }
}

// ============================ elementwise / scan =============================
__global__ __launch_bounds__(256) void conv_silu_kernel(
    const float* __restrict__ cw, const float* __restrict__ cb)
{
    const int d  = blockIdx.x * 256 + threadIdx.x;
    const int b  = blockIdx.z;
    const int t0 = blockIdx.y * 32;
    const float* xin = g_xz + (size_t)b * TLEN * (2 * DI) + d;
    float* xco = g_xconv + ((size_t)b * TLEN + t0) * DI + d;
    __nv_bfloat16* xch = g_xch + ((size_t)b * TLEN + t0) * DI + d;

    const float w0 = cw[d * 4 + 0], w1 = cw[d * 4 + 1];
    const float w2 = cw[d * 4 + 2], w3 = cw[d * 4 + 3];
    const float bias = cb[d];

    float xm3 = (t0 - 3 >= 0) ? xin[(size_t)(t0 - 3) * (2 * DI)] : 0.f;
    float xm2 = (t0 - 2 >= 0) ? xin[(size_t)(t0 - 2) * (2 * DI)] : 0.f;
    float xm1 = (t0 - 1 >= 0) ? xin[(size_t)(t0 - 1) * (2 * DI)] : 0.f;
#pragma unroll 4
    for (int tt = 0; tt < 32; tt++) {
        float xc = xin[(size_t)(t0 + tt) * (2 * DI)];
        float v = w0 * xm3 + w1 * xm2 + w2 * xm1 + w3 * xc + bias;
        float s = siluf_(v);
        xco[(size_t)tt * DI] = s;
        xch[(size_t)tt * DI] = __float2bfloat16_rn(s);
        xm3 = xm2; xm2 = xm1; xm1 = xc;
    }
}

// ---------------------------------------------------------------------------
// Fused B_ssm + dt + alpha. 512 blocks x 16 rows; warps split K 8-ways for
// the B_ssm MMA (SMEM-reduced) then split the dt loop 8-ways.
// ---------------------------------------------------------------------------
__global__ __launch_bounds__(256) void proj_alpha_kernel(const float* __restrict__ dtb)
{
    __shared__ float red[8][32][9];
    __shared__ float rsum[16];
    const int lane = threadIdx.x & 31, wid = threadIdx.x >> 5;
    const int rowbase = blockIdx.x * 16;
    const int r0 = rowbase + (lane >> 2);
    const int k0l = (lane & 3) * 2;
    const int nfr = (lane >> 2);
    const __nv_bfloat16* xr0 = g_xch + (size_t)r0 * DI;
    const __nv_bfloat16* xr8 = xr0 + (size_t)8 * DI;

    float c[2][4];
#pragma unroll
    for (int nt = 0; nt < 2; nt++)
#pragma unroll
        for (int q = 0; q < 4; q++) c[nt][q] = 0.f;

    const int ksbase = wid * 16;
#pragma unroll 4
    for (int ks = 0; ks < 16; ks++) {
        const int k0 = (ksbase + ks) * 16 + k0l;
        uint32_t a[4];
        a[0] = *(const uint32_t*)(xr0 + k0);
        a[1] = *(const uint32_t*)(xr8 + k0);
        a[2] = *(const uint32_t*)(xr0 + k0 + 8);
        a[3] = *(const uint32_t*)(xr8 + k0 + 8);
#pragma unroll
        for (int nt = 0; nt < 2; nt++) {
            const __nv_bfloat16* wn = g_xpwh + (size_t)(nt * 8 + nfr) * DI + k0;
            uint32_t b0 = *(const uint32_t*)(wn);
            uint32_t b1 = *(const uint32_t*)(wn + 8);
            mma16816(c[nt], a, b0, b1);
        }
    }
#pragma unroll
    for (int j = 0; j < 4; j++) {
        red[wid][lane][j]     = c[0][j];
        red[wid][lane][4 + j] = c[1][j];
    }
    if (threadIdx.x < 16) rsum[threadIdx.x] = 0.f;
    __syncthreads();

    float cf[8];
#pragma unroll
    for (int j = 0; j < 8; j++) {
        float s = 0.f;
#pragma unroll
        for (int w = 0; w < 8; w++) s += red[w][lane][j];
        cf[j] = s;
    }
    uint32_t a2[4];
    a2[0] = packbf2(cf[0], cf[1]);
    a2[1] = packbf2(cf[2], cf[3]);
    a2[2] = packbf2(cf[4], cf[5]);
    a2[3] = packbf2(cf[6], cf[7]);

    float sumA = 0.f, sumB = 0.f;
    const int ndbase = wid * 32;
#pragma unroll 4
    for (int nd = ndbase; nd < ndbase + 32; nd++) {
        const int n = nd * 8 + nfr;
        const __nv_bfloat16* wn = g_dtwh + (size_t)n * DS;
        uint32_t b0 = *(const uint32_t*)(wn + k0l);
        uint32_t b1 = *(const uint32_t*)(wn + k0l + 8);
        float cc[4] = {0.f, 0.f, 0.f, 0.f};
        mma16816(cc, a2, b0, b1);
        const int ncx = nd * 8 + k0l;
        float bb0 = dtb[ncx], bb1 = dtb[ncx + 1];
        sumA += softplusf_(cc[0] + bb0) + softplusf_(cc[1] + bb1);
        sumB += softplusf_(cc[2] + bb0) + softplusf_(cc[3] + bb1);
    }
    sumA += __shfl_xor_sync(0xffffffffu, sumA, 1);
    sumA += __shfl_xor_sync(0xffffffffu, sumA, 2);
    sumB += __shfl_xor_sync(0xffffffffu, sumB, 1);
    sumB += __shfl_xor_sync(0xffffffffu, sumB, 2);
    if ((lane & 3) == 0) {
        atomicAdd(&rsum[lane >> 2], sumA);
        atomicAdd(&rsum[8 + (lane >> 2)], sumB);
    }
    __syncthreads();
    if (threadIdx.x < 16)
        g_alpha[rowbase + threadIdx.x] =
            sigmoidf_(rsum[threadIdx.x] * (1.f / (float)DI));
}

__global__ __launch_bounds__(256) void scan1_kernel()
{
    const int d = blockIdx.x * 256 + threadIdx.x;
    const int c = blockIdx.y, b = blockIdx.z;
    const float* xc = g_xconv + ((size_t)b * TLEN + c * CL) * DI + d;
    const float* al = g_alpha + b * TLEN + c * CL;
    float h = 0.f;
#pragma unroll 8
    for (int tt = 0; tt < CL; tt++) {
        float a = al[tt];
        h = fmaf(a, h, (1.f - a) * xc[(size_t)tt * DI]);
    }
    g_S[((size_t)(b * NC + c)) * DI + d] = h;
}

__global__ __launch_bounds__(256) void scan2_kernel()
{
    const int id = blockIdx.x * 256 + threadIdx.x;
    const int b = id / DI, d = id % DI;
    __shared__ float Ps[NC];
    if (threadIdx.x < NC) {
        const float* al = g_alpha + b * TLEN + threadIdx.x * CL;
        float p = 1.f;
#pragma unroll
        for (int tt = 0; tt < CL; tt++) p *= al[tt];
        Ps[threadIdx.x] = p;
    }
    __syncthreads();
    float h = 0.f;
    g_H0[((size_t)(b * NC + 0)) * DI + d] = 0.f;
#pragma unroll 4
    for (int c = 0; c < NC - 1; c++) {
        h = fmaf(Ps[c], h, g_S[((size_t)(b * NC + c)) * DI + d]);
        g_H0[((size_t)(b * NC + c + 1)) * DI + d] = h;
    }
}

// seeded replay; z columns in g_xz already hold silu(z) (fused in in_proj).
__global__ __launch_bounds__(256) void scan3_kernel(const float* __restrict__ Dp)
{
    const int d = blockIdx.x * 256 + threadIdx.x;
    const int c = blockIdx.y, b = blockIdx.z;
    const size_t rbase = (size_t)b * TLEN + c * CL;
    const float* xc = g_xconv + rbase * DI + d;
    const float* zp = g_xz + rbase * (2 * DI) + DI + d;
    const float* al = g_alpha + b * TLEN + c * CL;
    __nv_bfloat16* yh = g_yh + rbase * DI + d;
    __nv_bfloat16* yl = g_yl + rbase * DI + d;
    const float Dv = Dp[d];
    float h = g_H0[((size_t)(b * NC + c)) * DI + d];
#pragma unroll 4
    for (int tt = 0; tt < CL; tt++) {
        float a = al[tt];
        float x = xc[(size_t)tt * DI];
        h = fmaf(a, h, (1.f - a) * x);
        float y = fmaf(h, Dv, x);
        y = y * zp[(size_t)tt * (2 * DI)];
        __nv_bfloat16 hh = __float2bfloat16_rn(y);
        yh[(size_t)tt * DI] = hh;
        yl[(size_t)tt * DI] = __float2bfloat16_rn(y - __bfloat162float(hh));
    }
}

// ---------------------------------------------------------------------------
extern "C" void kernel_launch(void* const* d_in, const int* in_sizes, int n_in,
                              void* d_out, int out_size)
{
    const float* x    = (const float*)d_in[0];
    const float* win  = (const float*)d_in[1];
    const float* cw   = (const float*)d_in[2];
    const float* cb   = (const float*)d_in[3];
    const float* xpw  = (const float*)d_in[4];
    const float* dtw  = (const float*)d_in[5];
    const float* dtb  = (const float*)d_in[6];
    const float* Dp   = (const float*)d_in[7];
    const float* wout = (const float*)d_in[8];
    float* out = (float*)d_out;

    float* xz; cudaGetSymbolAddress((void**)&xz, g_xz);
    __nv_bfloat16 *xh, *xl, *wih, *wil, *yh, *yl, *woh, *wol;
    cudaGetSymbolAddress((void**)&xh,  g_xh);
    cudaGetSymbolAddress((void**)&xl,  g_xl);
    cudaGetSymbolAddress((void**)&wih, g_wih);
    cudaGetSymbolAddress((void**)&wil, g_wil);
    cudaGetSymbolAddress((void**)&yh,  g_yh);
    cudaGetSymbolAddress((void**)&yl,  g_yl);
    cudaGetSymbolAddress((void**)&woh, g_woh);
    cudaGetSymbolAddress((void**)&wol, g_wol);

    cudaFuncSetAttribute(gemm3_bf, cudaFuncAttributeMaxDynamicSharedMemorySize,
                         GSMEM);

    // side stream + fork/join events (host objects; no device allocation)
    cudaStream_t s2;
    cudaStreamCreate(&s2);
    cudaEvent_t e1, e2;
    cudaEventCreateWithFlags(&e1, cudaEventDisableTiming);
    cudaEventCreateWithFlags(&e2, cudaEventDisableTiming);

    // 0) all operand conversions in one launch
    cvt_all_kernel<<<(CV_N4 + 255) / 256, 256>>>(x, win, wout, xpw, dtw);
    // 1a) in_proj x-half (cols 0..DI), persistent: 64x16 = 1024 tiles
    gemm3_bf<<<NPERS, 512, GSMEM>>>(
        xh, xl, wih, wil, xz, 2 * DI, DM, 1 << 30,
        DI / 128, 0, (MROWS / 128) * (DI / 128));
    // fork: z-half on side stream (non-persistent so CTAs retire and
    // interleave with the elementwise chain below)
    cudaEventRecord(e1, 0);
    cudaStreamWaitEvent(s2, e1, 0);
    // 1b) in_proj z-half (cols DI..2*DI), all silu'd: 1024 tiles, grid 1024
    gemm3_bf<<<(MROWS / 128) * (DI / 128), 512, GSMEM, s2>>>(
        xh, xl, wih, wil, xz, 2 * DI, DM, 0,
        DI / 128, DI / 128, (MROWS / 128) * (DI / 128));
    // 2-4 run concurrently with 1b (depend only on the x-half)
    conv_silu_kernel<<<dim3(DI / 256, TLEN / 32, BSZ), 256>>>(cw, cb);
    proj_alpha_kernel<<<MROWS / 16, 256>>>(dtb);
    scan1_kernel<<<dim3(DI / 256, NC, BSZ), 256>>>();
    scan2_kernel<<<MROWS / 256, 256>>>();
    // join: scan3 needs the z-half
    cudaEventRecord(e2, s2);
    cudaStreamWaitEvent(0, e2, 0);
    scan3_kernel<<<dim3(DI / 256, NC, BSZ), 256>>>(Dp);
    // 5) out_proj (persistent): 512 tiles
    gemm3_bf<<<NPERS, 512, GSMEM>>>(
        yh, yl, woh, wol, out, DM, DI, 1 << 30,
        DM / 128, 0, (MROWS / 128) * (DM / 128));
}